// round 11
// baseline (speedup 1.0000x reference)
#include <cuda_runtime.h>
#include <math.h>

#define NTOK 1032
#define EMB  768
#define NB   8
#define HEADS 12
#define MTOT (NB * NTOK)   // 8256
#define KPAD 1152          // 18 j-tiles * 64 = 9 i-tiles * 128
#define NJT  18
#define CEXP 0.18033688011112042f   // 0.125 * log2(e)

// Scratch (allocation-free)
__device__ float g_kv[(size_t)MTOT * 2 * EMB];             // [m][0:768)=k, [768:1536)=v
__device__ float g_ao[(size_t)MTOT * EMB];
__device__ unsigned g_kt[(size_t)NB * HEADS * KPAD * 64];  // tf32 K plain [bh][tok][d]
__device__ unsigned g_kf[(size_t)NB * HEADS * NJT * 4096]; // K fragment-major tiles
__device__ unsigned g_vf[(size_t)NB * HEADS * NJT * 4096]; // V^T fragment-major tiles
__device__ float g_btab[6272];   // [0,4225): exp(-.02(di^2+dl^2))*log2e ; rest zeros

__device__ __forceinline__ unsigned f2tf(float f) {
    unsigned r;
    asm("cvt.rna.tf32.f32 %0, %1;" : "=r"(r) : "f"(f));
    return r;
}
__device__ __forceinline__ float ex2(float x) {
    float r;
    asm("ex2.approx.f32 %0, %1;" : "=f"(r) : "f"(x));
    return r;
}
__device__ __forceinline__ void mma_tf32(float* c, const unsigned* a, unsigned b0, unsigned b1) {
    asm volatile(
        "mma.sync.aligned.m16n8k8.row.col.f32.tf32.tf32.f32 "
        "{%0,%1,%2,%3}, {%4,%5,%6,%7}, {%8,%9}, {%0,%1,%2,%3};"
        : "+f"(c[0]), "+f"(c[1]), "+f"(c[2]), "+f"(c[3])
        : "r"(a[0]), "r"(a[1]), "r"(a[2]), "r"(a[3]), "r"(b0), "r"(b1));
}
__device__ __forceinline__ void cp_async16(void* smem_dst, const void* gmem_src) {
    unsigned d = (unsigned)__cvta_generic_to_shared(smem_dst);
    asm volatile("cp.async.cg.shared.global [%0], [%1], 16;" :: "r"(d), "l"(gmem_src));
}
__device__ __forceinline__ void cp_commit() { asm volatile("cp.async.commit_group;"); }
__device__ __forceinline__ void cp_wait1()  { asm volatile("cp.async.wait_group 1;"); }

__global__ void init_btab(float* bt) {
    for (int i = threadIdx.x; i < 6272; i += 256) {
        float v = 0.0f;
        if (i < 4225) {
            int di = i / 65 - 32, dl = i % 65 - 32;
            v = __expf(-0.02f * (float)(di * di + dl * dl)) * 1.4426950408889634f;
        }
        bt[i] = v;
    }
}

// ---------------------------------------------------------------------------
// C[M,N] = A[M,K] @ W[N,K]^T + bias[N]   (tf32 tensor-core)
// ---------------------------------------------------------------------------
__global__ __launch_bounds__(256) void gemm_tf32(
    const float* __restrict__ A, const float* __restrict__ W,
    const float* __restrict__ bias, float* __restrict__ C,
    int M, int N, int K)
{
    __shared__ unsigned As[64][36];
    __shared__ unsigned Bs[128][36];

    const int tid = threadIdx.x;
    const int lane = tid & 31, wid = tid >> 5;
    const int g = lane >> 2, l = lane & 3;
    const int wm = (wid >> 2) * 32, wn = (wid & 3) * 32;
    const int m0 = blockIdx.y * 64, n0 = blockIdx.x * 128;

    float acc[2][4][4];
#pragma unroll
    for (int mt = 0; mt < 2; mt++)
#pragma unroll
        for (int nt = 0; nt < 4; nt++)
#pragma unroll
            for (int e = 0; e < 4; e++) acc[mt][nt][e] = 0.0f;

    const int NT = K / 32;
    const int rA0 = tid >> 3, qA0 = tid & 7;
    float4 ra[2], rb[4];

#define LOAD_TILE(KT)                                                          \
    {                                                                          \
        int kb = (KT) * 32;                                                    \
        _Pragma("unroll")                                                      \
        for (int i = 0; i < 2; i++)                                            \
            ra[i] = *(const float4*)(A + (size_t)(m0 + rA0 + i * 32) * K + kb + qA0 * 4); \
        _Pragma("unroll")                                                      \
        for (int i = 0; i < 4; i++)                                            \
            rb[i] = *(const float4*)(W + (size_t)(n0 + rA0 + i * 32) * K + kb + qA0 * 4); \
    }
#define STORE_TILE()                                                           \
    {                                                                          \
        _Pragma("unroll")                                                      \
        for (int i = 0; i < 2; i++) {                                          \
            unsigned* p = &As[rA0 + i * 32][qA0 * 4];                          \
            p[0] = f2tf(ra[i].x); p[1] = f2tf(ra[i].y);                        \
            p[2] = f2tf(ra[i].z); p[3] = f2tf(ra[i].w);                        \
        }                                                                      \
        _Pragma("unroll")                                                      \
        for (int i = 0; i < 4; i++) {                                          \
            unsigned* p = &Bs[rA0 + i * 32][qA0 * 4];                          \
            p[0] = f2tf(rb[i].x); p[1] = f2tf(rb[i].y);                        \
            p[2] = f2tf(rb[i].z); p[3] = f2tf(rb[i].w);                        \
        }                                                                      \
    }

    LOAD_TILE(0);
    STORE_TILE();
    __syncthreads();

    for (int kt = 0; kt < NT; kt++) {
        const bool more = (kt + 1) < NT;
        if (more) LOAD_TILE(kt + 1);

#pragma unroll
        for (int ks = 0; ks < 4; ks++) {
            int k0 = ks * 8;
            unsigned af[2][4], bf[4][2];
#pragma unroll
            for (int mt = 0; mt < 2; mt++) {
                int rr = wm + mt * 16 + g;
                af[mt][0] = As[rr][k0 + l];
                af[mt][1] = As[rr + 8][k0 + l];
                af[mt][2] = As[rr][k0 + 4 + l];
                af[mt][3] = As[rr + 8][k0 + 4 + l];
            }
#pragma unroll
            for (int nt = 0; nt < 4; nt++) {
                int cc = wn + nt * 8 + g;
                bf[nt][0] = Bs[cc][k0 + l];
                bf[nt][1] = Bs[cc][k0 + 4 + l];
            }
#pragma unroll
            for (int mt = 0; mt < 2; mt++)
#pragma unroll
                for (int nt = 0; nt < 4; nt++)
                    mma_tf32(acc[mt][nt], af[mt], bf[nt][0], bf[nt][1]);
        }
        __syncthreads();
        if (more) { STORE_TILE(); __syncthreads(); }
    }

#pragma unroll
    for (int mt = 0; mt < 2; mt++) {
#pragma unroll
        for (int nt = 0; nt < 4; nt++) {
            int row = m0 + wm + mt * 16 + g;
            int col = n0 + wn + nt * 8 + (l << 1);
            float b0 = bias[col], b1 = bias[col + 1];
            *(float2*)&C[(size_t)row * N + col] =
                make_float2(acc[mt][nt][0] + b0, acc[mt][nt][1] + b1);
            *(float2*)&C[(size_t)(row + 8) * N + col] =
                make_float2(acc[mt][nt][2] + b0, acc[mt][nt][3] + b1);
        }
    }
#undef LOAD_TILE
#undef STORE_TILE
}

// ---------------------------------------------------------------------------
// Repack: kv (f32) -> Kt plain tf32, Kf / Vf fragment-major tiles (as R10)
// ---------------------------------------------------------------------------
__global__ __launch_bounds__(256) void repack_kv(
    const float* __restrict__ kv, unsigned* __restrict__ Kt,
    unsigned* __restrict__ Kf, unsigned* __restrict__ Vf)
{
    __shared__ float sk[64][65];
    __shared__ float sv[64][65];
    const int tid = threadIdx.x;
    const int jt = blockIdx.x, h = blockIdx.y, b = blockIdx.z;
    const int j0 = jt * 64, bh = b * HEADS + h;

    const float* Kb = kv + (size_t)b * NTOK * (2 * EMB) + h * 64;
    const float* Vb = Kb + EMB;

#pragma unroll
    for (int i = 0; i < 4; i++) {
        int id = tid + i * 256;
        int r = id >> 4, q = (id & 15) << 2;
        int gj = j0 + r;
        float4 kk = make_float4(0.f, 0.f, 0.f, 0.f), vv = kk;
        if (gj < NTOK) {
            kk = *(const float4*)(Kb + (size_t)gj * (2 * EMB) + q);
            vv = *(const float4*)(Vb + (size_t)gj * (2 * EMB) + q);
        }
        uint4 ko = make_uint4(f2tf(kk.x), f2tf(kk.y), f2tf(kk.z), f2tf(kk.w));
        *(uint4*)&Kt[((size_t)bh * KPAD + j0 + r) * 64 + q] = ko;
        sk[r][q] = kk.x; sk[r][q + 1] = kk.y; sk[r][q + 2] = kk.z; sk[r][q + 3] = kk.w;
        sv[r][q] = vv.x; sv[r][q + 1] = vv.y; sv[r][q + 2] = vv.z; sv[r][q + 3] = vv.w;
    }
    __syncthreads();

    const int nt = tid >> 5, lane = tid & 31;
    const int g = lane >> 2, l = lane & 3;
    const int row = nt * 8 + g;
    const size_t fb = ((size_t)bh * NJT + jt) * 4096;
#pragma unroll
    for (int q = 0; q < 4; q++) {
        int c0 = 16 * q + l;
        uint4 kw = make_uint4(f2tf(sk[row][c0]),     f2tf(sk[row][c0 + 4]),
                              f2tf(sk[row][c0 + 8]), f2tf(sk[row][c0 + 12]));
        uint4 vw = make_uint4(f2tf(sv[c0][row]),     f2tf(sv[c0 + 4][row]),
                              f2tf(sv[c0 + 8][row]), f2tf(sv[c0 + 12][row]));
        size_t off = fb + ((size_t)(nt * 32 + lane) * 4 + q) * 4;
        *(uint4*)&Kf[off] = kw;
        *(uint4*)&Vf[off] = vw;
    }
}

// ---------------------------------------------------------------------------
// Flash attention, tf32 MMA. 256 thr (8 warps), i-tile 128, j-tile 64.
// P exchanged warp-internally via SHFL (C-layout -> A-layout), no smem P tile,
// no intra-tile syncs. Softmax of group n+1 overlaps PV MMAs of group n.
// smem: sK[2][5120] + sV[2][5120] = 81920 B.
// ---------------------------------------------------------------------------
#define FTBUF 5120

extern __shared__ unsigned smem_dyn[];

__global__ __launch_bounds__(256) void attn_tf32(
    const unsigned* __restrict__ Kt, const unsigned* __restrict__ Kf,
    const unsigned* __restrict__ Vf, const float* __restrict__ btab,
    float* __restrict__ out)
{
    unsigned* sK = smem_dyn;                   // 2 * FTBUF
    unsigned* sV = smem_dyn + 2 * FTBUF;       // 2 * FTBUF

    const int tid = threadIdx.x, lane = tid & 31, w = tid >> 5;
    const int g = lane >> 2, l = lane & 3, l2 = l << 1;
    const int i0 = blockIdx.x * 128, h = blockIdx.y, b = blockIdx.z;
    const int bh = b * HEADS + h;

    const unsigned* Ktb = Kt + (size_t)bh * KPAD * 64;
    const unsigned* Kfb = Kf + (size_t)bh * NJT * 4096;
    const unsigned* Vfb = Vf + (size_t)bh * NJT * 4096;

    // shuffle sources for C-layout -> A-layout P conversion
    const unsigned srcA = (lane & 28) | (l >> 1);
    const unsigned srcB = srcA + 2;
    const bool sel = (l & 1);

    auto stage = [&](int jts, int bufs) {
        const unsigned* gK = Kfb + (size_t)jts * 4096;
        const unsigned* gV = Vfb + (size_t)jts * 4096;
        unsigned* dK = sK + bufs * FTBUF;
        unsigned* dV = sV + bufs * FTBUF;
#pragma unroll
        for (int i = 0; i < 4; i++) {
            int cc = tid + i * 256;
            int sw = (cc >> 2) * 20 + (cc & 3) * 4;
            cp_async16(&dK[sw], &gK[cc * 4]);
            cp_async16(&dV[sw], &gV[cc * 4]);
        }
    };

    // ---- hoist Ki A-fragments from plain Kt (padded -> no bounds checks) ----
    const int r0 = i0 + w * 16 + g;
    unsigned ka[8][4];
#pragma unroll
    for (int ks = 0; ks < 8; ks++) {
        int k0 = ks * 8;
        ka[ks][0] = Ktb[(size_t)r0 * 64 + k0 + l];
        ka[ks][1] = Ktb[(size_t)(r0 + 8) * 64 + k0 + l];
        ka[ks][2] = Ktb[(size_t)r0 * 64 + k0 + 4 + l];
        ka[ks][3] = Ktb[(size_t)(r0 + 8) * 64 + k0 + 4 + l];
    }

    float oacc[8][4];
#pragma unroll
    for (int nt = 0; nt < 8; nt++)
#pragma unroll
        for (int e = 0; e < 4; e++) oacc[nt][e] = 0.0f;
    float l0r = 0.0f, l1r = 0.0f;

    const int gi0 = r0, gi1 = r0 + 8;
    const int rb0 = (gi0 >= 8) ? ((((gi0 - 8) >> 5) + 32) * 65 + ((gi0 - 8) & 31) + 32) : 6271;
    const int rb1 = (gi1 >= 8) ? ((((gi1 - 8) >> 5) + 32) * 65 + ((gi1 - 8) & 31) + 32) : 6271;

    stage(0, 0);
    cp_commit();

// S-MMA for 4 nt groups (B frags from fragment-major smem, 20-word lane stride)
#define SGRP(SB, N0G)                                                          \
    {                                                                          \
        uint4 fr[4][4];                                                        \
        _Pragma("unroll")                                                      \
        for (int t = 0; t < 4; t++) {                                          \
            const uint4* bp = (const uint4*)((SB) + (((N0G) + t) * 32 + lane) * 20); \
            fr[t][0] = bp[0]; fr[t][1] = bp[1]; fr[t][2] = bp[2]; fr[t][3] = bp[3]; \
        }                                                                      \
        _Pragma("unroll")                                                      \
        for (int ks = 0; ks < 8; ks++) {                                       \
            const int q = ks >> 1; const int od = ks & 1;                      \
            _Pragma("unroll")                                                  \
            for (int t = 0; t < 4; t++)                                        \
                mma_tf32(sacc[(N0G) + t], ka[ks],                              \
                         od ? fr[t][q].z : fr[t][q].x,                         \
                         od ? fr[t][q].w : fr[t][q].y);                        \
        }                                                                      \
    }

// S-MMA for nt group 0 only (LAST tile)
#define SGRP1(SB)                                                              \
    {                                                                          \
        const uint4* bp = (const uint4*)((SB) + (size_t)lane * 20);            \
        uint4 fr0 = bp[0], fr1 = bp[1], fr2 = bp[2], fr3 = bp[3];              \
        mma_tf32(sacc[0], ka[0], fr0.x, fr0.y);                                \
        mma_tf32(sacc[0], ka[1], fr0.z, fr0.w);                                \
        mma_tf32(sacc[0], ka[2], fr1.x, fr1.y);                                \
        mma_tf32(sacc[0], ka[3], fr1.z, fr1.w);                                \
        mma_tf32(sacc[0], ka[4], fr2.x, fr2.y);                                \
        mma_tf32(sacc[0], ka[5], fr2.z, fr2.w);                                \
        mma_tf32(sacc[0], ka[6], fr3.x, fr3.y);                                \
        mma_tf32(sacc[0], ka[7], fr3.z, fr3.w);                                \
    }

// softmax for S group KS + C->A layout shuffle conversion into AF[4]
#define SMAXKS(KS, WB, AF)                                                     \
    {                                                                          \
        float b00, b01, b10, b11;                                              \
        if (WB) {                                                              \
            int u0 = j0 + (KS) * 8 + l2 - 8;                                   \
            int t0i = (u0 >> 5) * 65 + (u0 & 31);                              \
            int u1 = u0 + 1;                                                   \
            int t1i = (u1 >> 5) * 65 + (u1 & 31);                              \
            b00 = __ldg(&btab[rb0 - t0i]); b01 = __ldg(&btab[rb0 - t1i]);      \
            b10 = __ldg(&btab[rb1 - t0i]); b11 = __ldg(&btab[rb1 - t1i]);      \
        } else { b00 = b01 = b10 = b11 = 0.0f; }                               \
        float p00 = ex2(fmaf(sacc[KS][0], CEXP, b00));                         \
        float p01 = ex2(fmaf(sacc[KS][1], CEXP, b01));                         \
        float p10 = ex2(fmaf(sacc[KS][2], CEXP, b10));                         \
        float p11 = ex2(fmaf(sacc[KS][3], CEXP, b11));                         \
        s0 += p00 + p01; s1 += p10 + p11;                                      \
        unsigned c0 = f2tf(p00), c1 = f2tf(p01), c2 = f2tf(p10), c3 = f2tf(p11); \
        unsigned ua, ub;                                                       \
        ua = __shfl_sync(0xffffffffu, c0, srcA);                               \
        ub = __shfl_sync(0xffffffffu, c1, srcA);                               \
        AF[0] = sel ? ub : ua;                                                 \
        ua = __shfl_sync(0xffffffffu, c2, srcA);                               \
        ub = __shfl_sync(0xffffffffu, c3, srcA);                               \
        AF[1] = sel ? ub : ua;                                                 \
        ua = __shfl_sync(0xffffffffu, c0, srcB);                               \
        ub = __shfl_sync(0xffffffffu, c1, srcB);                               \
        AF[2] = sel ? ub : ua;                                                 \
        ua = __shfl_sync(0xffffffffu, c2, srcB);                               \
        ub = __shfl_sync(0xffffffffu, c3, srcB);                               \
        AF[3] = sel ? ub : ua;                                                 \
    }

// one k-pair of PV: V frags for k-groups {2*QP, 2*QP+1}, softmax interleaved
#define PVHALF(QP, WBE)                                                        \
    {                                                                          \
        uint4 bv[8];                                                           \
        _Pragma("unroll")                                                      \
        for (int t = 0; t < 8; t++)                                            \
            bv[t] = *(const uint4*)(sVb + ((t * 32 + lane) * 20) + (QP) * 4);  \
        unsigned af[4];                                                        \
        SMAXKS(2 * (QP), WBE, af);                                             \
        _Pragma("unroll")                                                      \
        for (int t = 0; t < 8; t++)                                            \
            mma_tf32(oacc[t], af, bv[t].x, bv[t].y);                           \
        SMAXKS(2 * (QP) + 1, 1, af);                                           \
        _Pragma("unroll")                                                      \
        for (int t = 0; t < 8; t++)                                            \
            mma_tf32(oacc[t], af, bv[t].z, bv[t].w);                           \
    }

// one tile. MODE: 0 = FIRST (jt 0), 1 = MID, 2 = LAST (jt 16, only nt0 live)
#define TILE(JT, MODE)                                                         \
    {                                                                          \
        const int jt = (JT);                                                   \
        const int buf = jt & 1;                                                \
        if (jt < 16) stage(jt + 1, buf ^ 1);                                   \
        cp_commit();                                                           \
        cp_wait1();                                                            \
        __syncthreads();                                                       \
        const unsigned* sKb = sK + buf * FTBUF;                                \
        const unsigned* sVb = sV + buf * FTBUF;                                \
        const int j0 = jt * 64;                                                \
        float sacc[8][4];                                                      \
        _Pragma("unroll")                                                      \
        for (int nt = 0; nt < 8; nt++) {                                       \
            sacc[nt][0] = 0.f; sacc[nt][1] = 0.f;                              \
            sacc[nt][2] = 0.f; sacc[nt][3] = 0.f;                              \
        }                                                                      \
        float s0 = 0.0f, s1 = 0.0f;                                            \
        if (MODE == 2) {                                                       \
            SGRP1(sKb);                                                        \
            uint4 bv[8];                                                       \
            _Pragma("unroll")                                                  \
            for (int t = 0; t < 8; t++)                                        \
                bv[t] = *(const uint4*)(sVb + ((t * 32 + lane) * 20));         \
            unsigned af[4];                                                    \
            SMAXKS(0, 1, af);                                                  \
            _Pragma("unroll")                                                  \
            for (int t = 0; t < 8; t++)                                        \
                mma_tf32(oacc[t], af, bv[t].x, bv[t].y);                       \
        } else {                                                               \
            SGRP(sKb, 0);                                                      \
            SGRP(sKb, 4);                                                      \
            PVHALF(0, (MODE != 0));                                            \
            PVHALF(1, 1);                                                      \
            PVHALF(2, 1);                                                      \
            PVHALF(3, 1);                                                      \
        }                                                                      \
        s0 += __shfl_xor_sync(0xffffffffu, s0, 1);                             \
        s0 += __shfl_xor_sync(0xffffffffu, s0, 2);                             \
        s1 += __shfl_xor_sync(0xffffffffu, s1, 1);                             \
        s1 += __shfl_xor_sync(0xffffffffu, s1, 2);                             \
        l0r += s0; l1r += s1;                                                  \
        __syncthreads();                                                       \
    }

    TILE(0, 0);
#pragma unroll 1
    for (int jtm = 1; jtm < 16; jtm++) TILE(jtm, 1);
    TILE(16, 2);

    // ---- epilogue ----
    float inv0 = 1.0f / l0r, inv1 = 1.0f / l1r;
#pragma unroll
    for (int nt = 0; nt < 8; nt++) {
        int d = h * 64 + nt * 8 + l2;
        if (gi0 < NTOK)
            *(float2*)&out[((size_t)b * NTOK + gi0) * EMB + d] =
                make_float2(oacc[nt][0] * inv0, oacc[nt][1] * inv0);
        if (gi1 < NTOK)
            *(float2*)&out[((size_t)b * NTOK + gi1) * EMB + d] =
                make_float2(oacc[nt][2] * inv1, oacc[nt][3] * inv1);
    }
}

// ---------------------------------------------------------------------------
extern "C" void kernel_launch(void* const* d_in, const int* in_sizes, int n_in,
                              void* d_out, int out_size)
{
    const float* x      = (const float*)d_in[0];
    const float* qkv_w  = (const float*)d_in[1];  // [2304, 768]
    const float* qkv_b  = (const float*)d_in[2];  // [2304]
    const float* proj_w = (const float*)d_in[3];  // [768, 768]
    const float* proj_b = (const float*)d_in[4];  // [768]
    float* out = (float*)d_out;

    float *kvp = nullptr, *aop = nullptr, *btp = nullptr;
    unsigned *ktp = nullptr, *kfp = nullptr, *vfp = nullptr;
    cudaGetSymbolAddress((void**)&kvp, g_kv);
    cudaGetSymbolAddress((void**)&aop, g_ao);
    cudaGetSymbolAddress((void**)&btp, g_btab);
    cudaGetSymbolAddress((void**)&ktp, g_kt);
    cudaGetSymbolAddress((void**)&kfp, g_kf);
    cudaGetSymbolAddress((void**)&vfp, g_vf);

    const int attn_smem = 4 * FTBUF * 4;   // 81920 B

    static bool attr_set = false;
    if (!attr_set) {
        cudaFuncSetAttribute(attn_tf32, cudaFuncAttributeMaxDynamicSharedMemorySize,
                             attn_smem);
        attr_set = true;
    }

    init_btab<<<1, 256>>>(btp);

    // 1) kv = x @ qkv_w[768:2304].T + qkv_b[768:2304]   (q slice unused)
    gemm_tf32<<<dim3(1536 / 128, MTOT / 64), 256>>>(
        x, qkv_w + (size_t)768 * 768, qkv_b + 768, kvp, MTOT, 1536, 768);

    // 2) repack: plain Kt + fragment-major Kf/Vf tiles
    repack_kv<<<dim3(NJT, HEADS, NB), 256>>>(kvp, ktp, kfp, vfp);

    // 3) flash attention (shuffle P exchange, no smem P)
    attn_tf32<<<dim3(KPAD / 128, HEADS, NB), 256, attn_smem>>>(
        ktp, kfp, vfp, btp, aop);

    // 4) out = ao @ proj_w.T + proj_b
    gemm_tf32<<<dim3(768 / 128, MTOT / 64), 256>>>(
        aop, proj_w, proj_b, out, MTOT, 768, 768);
}

// round 12
// speedup vs baseline: 1.1580x; 1.1580x over previous
#include <cuda_runtime.h>
#include <math.h>

#define NTOK 1032
#define EMB  768
#define NB   8
#define HEADS 12
#define MTOT (NB * NTOK)   // 8256
#define KPAD 1152          // 18 j-tiles * 64 = 9 i-tiles * 128
#define NJT  18
#define CEXP 0.18033688011112042f   // 0.125 * log2(e)

// Scratch (allocation-free)
__device__ float g_kv[(size_t)MTOT * 2 * EMB];             // [m][0:768)=k, [768:1536)=v
__device__ float g_ao[(size_t)MTOT * EMB];
__device__ unsigned g_kt[(size_t)NB * HEADS * KPAD * 64];  // tf32 K plain [bh][tok][d]
__device__ unsigned g_kf[(size_t)NB * HEADS * NJT * 4096]; // K fragment tiles (q-major)
__device__ unsigned g_vf[(size_t)NB * HEADS * NJT * 4096]; // V^T fragment tiles (q-major)
__device__ float g_btab[6272];   // [0,4225): exp(-.02(di^2+dl^2))*log2e ; rest zeros

__device__ __forceinline__ unsigned f2tf(float f) {
    unsigned r;
    asm("cvt.rna.tf32.f32 %0, %1;" : "=r"(r) : "f"(f));
    return r;
}
__device__ __forceinline__ float ex2(float x) {
    float r;
    asm("ex2.approx.f32 %0, %1;" : "=f"(r) : "f"(x));
    return r;
}
__device__ __forceinline__ void mma_tf32(float* c, const unsigned* a, unsigned b0, unsigned b1) {
    asm volatile(
        "mma.sync.aligned.m16n8k8.row.col.f32.tf32.tf32.f32 "
        "{%0,%1,%2,%3}, {%4,%5,%6,%7}, {%8,%9}, {%0,%1,%2,%3};"
        : "+f"(c[0]), "+f"(c[1]), "+f"(c[2]), "+f"(c[3])
        : "r"(a[0]), "r"(a[1]), "r"(a[2]), "r"(a[3]), "r"(b0), "r"(b1));
}
__device__ __forceinline__ void cp_async16(void* smem_dst, const void* gmem_src) {
    unsigned d = (unsigned)__cvta_generic_to_shared(smem_dst);
    asm volatile("cp.async.cg.shared.global [%0], [%1], 16;" :: "r"(d), "l"(gmem_src));
}
__device__ __forceinline__ void cp_commit() { asm volatile("cp.async.commit_group;"); }
__device__ __forceinline__ void cp_wait1()  { asm volatile("cp.async.wait_group 1;"); }

__global__ void init_btab(float* bt) {
    for (int i = threadIdx.x; i < 6272; i += 256) {
        float v = 0.0f;
        if (i < 4225) {
            int di = i / 65 - 32, dl = i % 65 - 32;
            v = __expf(-0.02f * (float)(di * di + dl * dl)) * 1.4426950408889634f;
        }
        bt[i] = v;
    }
}

// ---------------------------------------------------------------------------
// C[M,N] = A[M,K] @ W[N,K]^T + bias[N]   (tf32 tensor-core)
// ---------------------------------------------------------------------------
__global__ __launch_bounds__(256) void gemm_tf32(
    const float* __restrict__ A, const float* __restrict__ W,
    const float* __restrict__ bias, float* __restrict__ C,
    int M, int N, int K)
{
    __shared__ unsigned As[64][36];
    __shared__ unsigned Bs[128][36];

    const int tid = threadIdx.x;
    const int lane = tid & 31, wid = tid >> 5;
    const int g = lane >> 2, l = lane & 3;
    const int wm = (wid >> 2) * 32, wn = (wid & 3) * 32;
    const int m0 = blockIdx.y * 64, n0 = blockIdx.x * 128;

    float acc[2][4][4];
#pragma unroll
    for (int mt = 0; mt < 2; mt++)
#pragma unroll
        for (int nt = 0; nt < 4; nt++)
#pragma unroll
            for (int e = 0; e < 4; e++) acc[mt][nt][e] = 0.0f;

    const int NT = K / 32;
    const int rA0 = tid >> 3, qA0 = tid & 7;
    float4 ra[2], rb[4];

#define LOAD_TILE(KT)                                                          \
    {                                                                          \
        int kb = (KT) * 32;                                                    \
        _Pragma("unroll")                                                      \
        for (int i = 0; i < 2; i++)                                            \
            ra[i] = *(const float4*)(A + (size_t)(m0 + rA0 + i * 32) * K + kb + qA0 * 4); \
        _Pragma("unroll")                                                      \
        for (int i = 0; i < 4; i++)                                            \
            rb[i] = *(const float4*)(W + (size_t)(n0 + rA0 + i * 32) * K + kb + qA0 * 4); \
    }
#define STORE_TILE()                                                           \
    {                                                                          \
        _Pragma("unroll")                                                      \
        for (int i = 0; i < 2; i++) {                                          \
            unsigned* p = &As[rA0 + i * 32][qA0 * 4];                          \
            p[0] = f2tf(ra[i].x); p[1] = f2tf(ra[i].y);                        \
            p[2] = f2tf(ra[i].z); p[3] = f2tf(ra[i].w);                        \
        }                                                                      \
        _Pragma("unroll")                                                      \
        for (int i = 0; i < 4; i++) {                                          \
            unsigned* p = &Bs[rA0 + i * 32][qA0 * 4];                          \
            p[0] = f2tf(rb[i].x); p[1] = f2tf(rb[i].y);                        \
            p[2] = f2tf(rb[i].z); p[3] = f2tf(rb[i].w);                        \
        }                                                                      \
    }

    LOAD_TILE(0);
    STORE_TILE();
    __syncthreads();

    for (int kt = 0; kt < NT; kt++) {
        const bool more = (kt + 1) < NT;
        if (more) LOAD_TILE(kt + 1);

#pragma unroll
        for (int ks = 0; ks < 4; ks++) {
            int k0 = ks * 8;
            unsigned af[2][4], bf[4][2];
#pragma unroll
            for (int mt = 0; mt < 2; mt++) {
                int rr = wm + mt * 16 + g;
                af[mt][0] = As[rr][k0 + l];
                af[mt][1] = As[rr + 8][k0 + l];
                af[mt][2] = As[rr][k0 + 4 + l];
                af[mt][3] = As[rr + 8][k0 + 4 + l];
            }
#pragma unroll
            for (int nt = 0; nt < 4; nt++) {
                int cc = wn + nt * 8 + g;
                bf[nt][0] = Bs[cc][k0 + l];
                bf[nt][1] = Bs[cc][k0 + 4 + l];
            }
#pragma unroll
            for (int mt = 0; mt < 2; mt++)
#pragma unroll
                for (int nt = 0; nt < 4; nt++)
                    mma_tf32(acc[mt][nt], af[mt], bf[nt][0], bf[nt][1]);
        }
        __syncthreads();
        if (more) { STORE_TILE(); __syncthreads(); }
    }

#pragma unroll
    for (int mt = 0; mt < 2; mt++) {
#pragma unroll
        for (int nt = 0; nt < 4; nt++) {
            int row = m0 + wm + mt * 16 + g;
            int col = n0 + wn + nt * 8 + (l << 1);
            float b0 = bias[col], b1 = bias[col + 1];
            *(float2*)&C[(size_t)row * N + col] =
                make_float2(acc[mt][nt][0] + b0, acc[mt][nt][1] + b1);
            *(float2*)&C[(size_t)(row + 8) * N + col] =
                make_float2(acc[mt][nt][2] + b0, acc[mt][nt][3] + b1);
        }
    }
#undef LOAD_TILE
#undef STORE_TILE
}

// ---------------------------------------------------------------------------
// Repack: kv (f32) -> Kt plain tf32; Kf/Vf fragment tiles, q-major chunks:
//   chunk for (nt, lane, q) at word offset nt*512 + q*128 + lane*4
//   (lanes of one LDS.128 phase hit distinct chunk banks -> no padding needed)
//   chunk words: [K[row][16q+l], K[row][16q+4+l], K[row][16q+8+l], K[row][16q+12+l]]
//   with row = nt*8+g  (Vf: same with V^T, i.e. sv[col][row])
// ---------------------------------------------------------------------------
__global__ __launch_bounds__(256) void repack_kv(
    const float* __restrict__ kv, unsigned* __restrict__ Kt,
    unsigned* __restrict__ Kf, unsigned* __restrict__ Vf)
{
    __shared__ float sk[64][65];
    __shared__ float sv[64][65];
    const int tid = threadIdx.x;
    const int jt = blockIdx.x, h = blockIdx.y, b = blockIdx.z;
    const int j0 = jt * 64, bh = b * HEADS + h;

    const float* Kb = kv + (size_t)b * NTOK * (2 * EMB) + h * 64;
    const float* Vb = Kb + EMB;

#pragma unroll
    for (int i = 0; i < 4; i++) {
        int id = tid + i * 256;
        int r = id >> 4, q = (id & 15) << 2;
        int gj = j0 + r;
        float4 kk = make_float4(0.f, 0.f, 0.f, 0.f), vv = kk;
        if (gj < NTOK) {
            kk = *(const float4*)(Kb + (size_t)gj * (2 * EMB) + q);
            vv = *(const float4*)(Vb + (size_t)gj * (2 * EMB) + q);
        }
        uint4 ko = make_uint4(f2tf(kk.x), f2tf(kk.y), f2tf(kk.z), f2tf(kk.w));
        *(uint4*)&Kt[((size_t)bh * KPAD + j0 + r) * 64 + q] = ko;
        sk[r][q] = kk.x; sk[r][q + 1] = kk.y; sk[r][q + 2] = kk.z; sk[r][q + 3] = kk.w;
        sv[r][q] = vv.x; sv[r][q + 1] = vv.y; sv[r][q + 2] = vv.z; sv[r][q + 3] = vv.w;
    }
    __syncthreads();

    const int nt = tid >> 5, lane = tid & 31;
    const int g = lane >> 2, l = lane & 3;
    const int row = nt * 8 + g;
    const size_t fb = ((size_t)bh * NJT + jt) * 4096;
#pragma unroll
    for (int q = 0; q < 4; q++) {
        int c0 = 16 * q + l;
        uint4 kw = make_uint4(f2tf(sk[row][c0]),     f2tf(sk[row][c0 + 4]),
                              f2tf(sk[row][c0 + 8]), f2tf(sk[row][c0 + 12]));
        uint4 vw = make_uint4(f2tf(sv[c0][row]),     f2tf(sv[c0 + 4][row]),
                              f2tf(sv[c0 + 8][row]), f2tf(sv[c0 + 12][row]));
        size_t off = fb + (size_t)(nt * 512 + q * 128 + lane * 4);
        *(uint4*)&Kf[off] = kw;
        *(uint4*)&Vf[off] = vw;
    }
}

// ---------------------------------------------------------------------------
// Flash attention, tf32 MMA. 256 thr (8 warps), i-tile 128, j-tile 64.
// Q-major fragment smem (no padding), smem P tile, split-half S/softmax to
// cut live registers. __launch_bounds__(256,2) -> 2 CTAs/SM (the round's
// target: occupancy 12.5% -> 25%).
// smem: sK[2][4096] + sV[2][4096] + sP[128][68] = 100352 B (2 CTAs = 196 KB)
// ---------------------------------------------------------------------------
#define FTBUF 4096
#define STR 68

extern __shared__ unsigned smem_dyn[];

__global__ __launch_bounds__(256, 2) void attn_tf32(
    const unsigned* __restrict__ Kt, const unsigned* __restrict__ Kf,
    const unsigned* __restrict__ Vf, const float* __restrict__ btab,
    float* __restrict__ out)
{
    unsigned* sK = smem_dyn;                   // 2 * FTBUF
    unsigned* sV = smem_dyn + 2 * FTBUF;       // 2 * FTBUF
    unsigned* sP = smem_dyn + 4 * FTBUF;       // 128 * STR

    const int tid = threadIdx.x, lane = tid & 31, w = tid >> 5;
    const int g = lane >> 2, l = lane & 3, l2 = l << 1;
    const int i0 = blockIdx.x * 128, h = blockIdx.y, b = blockIdx.z;
    const int bh = b * HEADS + h;

    const unsigned* Ktb = Kt + (size_t)bh * KPAD * 64;
    const unsigned* Kfb = Kf + (size_t)bh * NJT * 4096;
    const unsigned* Vfb = Vf + (size_t)bh * NJT * 4096;

    auto stage = [&](int jts, int bufs) {
        const unsigned* gK = Kfb + (size_t)jts * 4096;
        const unsigned* gV = Vfb + (size_t)jts * 4096;
        unsigned* dK = sK + bufs * FTBUF;
        unsigned* dV = sV + bufs * FTBUF;
#pragma unroll
        for (int i = 0; i < 4; i++) {
            int cc = (tid + i * 256) * 4;      // identity copy, q-major layout
            cp_async16(&dK[cc], &gK[cc]);
            cp_async16(&dV[cc], &gV[cc]);
        }
    };

    // ---- hoist Ki A-fragments from plain Kt (padded -> no bounds checks) ----
    const int r0 = i0 + w * 16 + g;
    unsigned ka[8][4];
#pragma unroll
    for (int ks = 0; ks < 8; ks++) {
        int k0 = ks * 8;
        ka[ks][0] = Ktb[(size_t)r0 * 64 + k0 + l];
        ka[ks][1] = Ktb[(size_t)(r0 + 8) * 64 + k0 + l];
        ka[ks][2] = Ktb[(size_t)r0 * 64 + k0 + 4 + l];
        ka[ks][3] = Ktb[(size_t)(r0 + 8) * 64 + k0 + 4 + l];
    }

    float oacc[8][4];
#pragma unroll
    for (int nt = 0; nt < 8; nt++)
#pragma unroll
        for (int e = 0; e < 4; e++) oacc[nt][e] = 0.0f;
    float l0r = 0.0f, l1r = 0.0f;

    const int gi0 = r0, gi1 = r0 + 8;
    const int rb0 = (gi0 >= 8) ? ((((gi0 - 8) >> 5) + 32) * 65 + ((gi0 - 8) & 31) + 32) : 6271;
    const int rb1 = (gi1 >= 8) ? ((((gi1 - 8) >> 5) + 32) * 65 + ((gi1 - 8) & 31) + 32) : 6271;
    const int prow = w * 16 + g;

    stage(0, 0);
    cp_commit();

// S-MMA for 4 nt groups starting at N0G. sacc = float[4][4].
#define SGRP(SB, N0G)                                                          \
    {                                                                          \
        uint4 fr[4][4];                                                        \
        _Pragma("unroll")                                                      \
        for (int t = 0; t < 4; t++)                                            \
            _Pragma("unroll")                                                  \
            for (int q = 0; q < 4; q++)                                        \
                fr[t][q] = *(const uint4*)((SB) + ((N0G) + t) * 512 + q * 128 + lane * 4); \
        _Pragma("unroll")                                                      \
        for (int ks = 0; ks < 8; ks++) {                                       \
            const int q = ks >> 1; const int od = ks & 1;                      \
            _Pragma("unroll")                                                  \
            for (int t = 0; t < 4; t++)                                        \
                mma_tf32(sacc[t], ka[ks],                                      \
                         od ? fr[t][q].z : fr[t][q].x,                         \
                         od ? fr[t][q].w : fr[t][q].y);                        \
        }                                                                      \
    }

// softmax for global nt-group NT (sacc index NT&3). WB: 0 = no bias.
#define SMAXNT(NT, WB)                                                         \
    {                                                                          \
        float b00, b01, b10, b11;                                              \
        if (WB) {                                                              \
            int u0 = j0 + (NT) * 8 + l2 - 8;                                   \
            int t0i = (u0 >> 5) * 65 + (u0 & 31);                              \
            int u1 = u0 + 1;                                                   \
            int t1i = (u1 >> 5) * 65 + (u1 & 31);                              \
            b00 = __ldg(&btab[rb0 - t0i]); b01 = __ldg(&btab[rb0 - t1i]);      \
            b10 = __ldg(&btab[rb1 - t0i]); b11 = __ldg(&btab[rb1 - t1i]);      \
        } else { b00 = b01 = b10 = b11 = 0.0f; }                               \
        float p00 = ex2(fmaf(sacc[(NT) & 3][0], CEXP, b00));                   \
        float p01 = ex2(fmaf(sacc[(NT) & 3][1], CEXP, b01));                   \
        float p10 = ex2(fmaf(sacc[(NT) & 3][2], CEXP, b10));                   \
        float p11 = ex2(fmaf(sacc[(NT) & 3][3], CEXP, b11));                   \
        s0 += p00 + p01; s1 += p10 + p11;                                      \
        *(uint2*)&sP[prow * STR + (NT) * 8 + l2] = make_uint2(f2tf(p00), f2tf(p01)); \
        *(uint2*)&sP[(prow + 8) * STR + (NT) * 8 + l2] = make_uint2(f2tf(p10), f2tf(p11)); \
    }

// one tile. MODE: 0 = FIRST (jt 0), 1 = MID, 2 = LAST (jt 16, only nt0 live)
#define TILE(JT, MODE)                                                         \
    {                                                                          \
        const int jt = (JT);                                                   \
        const int buf = jt & 1;                                                \
        if (jt < 16) stage(jt + 1, buf ^ 1);                                   \
        cp_commit();                                                           \
        cp_wait1();                                                            \
        __syncthreads();                                                       \
        const unsigned* sKb = sK + buf * FTBUF;                                \
        const unsigned* sVb = sV + buf * FTBUF;                                \
        const int j0 = jt * 64;                                                \
        float s0 = 0.0f, s1 = 0.0f;                                            \
        float sacc[4][4];                                                      \
        if (MODE == 2) {                                                       \
            _Pragma("unroll")                                                  \
            for (int e = 0; e < 4; e++) sacc[0][e] = 0.0f;                     \
            {                                                                  \
                const uint4* bp0 = (const uint4*)(sKb + lane * 4);             \
                _Pragma("unroll")                                              \
                for (int ks = 0; ks < 8; ks++) {                               \
                    uint4 f = bp0[(ks >> 1) * 32];                             \
                    mma_tf32(sacc[0], ka[ks],                                  \
                             (ks & 1) ? f.z : f.x, (ks & 1) ? f.w : f.y);      \
                }                                                              \
            }                                                                  \
            SMAXNT(0, 1);                                                      \
            s0 += __shfl_xor_sync(0xffffffffu, s0, 1);                         \
            s0 += __shfl_xor_sync(0xffffffffu, s0, 2);                         \
            s1 += __shfl_xor_sync(0xffffffffu, s1, 1);                         \
            s1 += __shfl_xor_sync(0xffffffffu, s1, 2);                         \
            l0r += s0; l1r += s1;                                              \
            __syncwarp();                                                      \
            unsigned pa[4];                                                    \
            pa[0] = sP[prow * STR + l];                                        \
            pa[1] = sP[(prow + 8) * STR + l];                                  \
            pa[2] = sP[prow * STR + 4 + l];                                    \
            pa[3] = sP[(prow + 8) * STR + 4 + l];                              \
            _Pragma("unroll")                                                  \
            for (int t = 0; t < 8; t++) {                                      \
                uint4 f = *(const uint4*)(sVb + t * 512 + lane * 4);           \
                mma_tf32(oacc[t], pa, f.x, f.y);                               \
            }                                                                  \
        } else {                                                               \
            _Pragma("unroll")                                                  \
            for (int t = 0; t < 4; t++)                                        \
                _Pragma("unroll")                                              \
                for (int e = 0; e < 4; e++) sacc[t][e] = 0.0f;                 \
            SGRP(sKb, 0);                                                      \
            SMAXNT(0, (MODE != 0));                                            \
            SMAXNT(1, 1); SMAXNT(2, 1); SMAXNT(3, 1);                          \
            _Pragma("unroll")                                                  \
            for (int t = 0; t < 4; t++)                                        \
                _Pragma("unroll")                                              \
                for (int e = 0; e < 4; e++) sacc[t][e] = 0.0f;                 \
            SGRP(sKb, 4);                                                      \
            SMAXNT(4, 1); SMAXNT(5, 1); SMAXNT(6, 1); SMAXNT(7, 1);            \
            s0 += __shfl_xor_sync(0xffffffffu, s0, 1);                         \
            s0 += __shfl_xor_sync(0xffffffffu, s0, 2);                         \
            s1 += __shfl_xor_sync(0xffffffffu, s1, 1);                         \
            s1 += __shfl_xor_sync(0xffffffffu, s1, 2);                         \
            l0r += s0; l1r += s1;                                              \
            __syncwarp();                                                      \
            unsigned paf[8][4];                                                \
            _Pragma("unroll")                                                  \
            for (int ks = 0; ks < 8; ks++) {                                   \
                int k0 = ks * 8;                                               \
                paf[ks][0] = sP[prow * STR + k0 + l];                          \
                paf[ks][1] = sP[(prow + 8) * STR + k0 + l];                    \
                paf[ks][2] = sP[prow * STR + k0 + 4 + l];                      \
                paf[ks][3] = sP[(prow + 8) * STR + k0 + 4 + l];                \
            }                                                                  \
            _Pragma("unroll")                                                  \
            for (int t = 0; t < 8; t++) {                                      \
                uint4 fv[4];                                                   \
                _Pragma("unroll")                                              \
                for (int q = 0; q < 4; q++)                                    \
                    fv[q] = *(const uint4*)(sVb + t * 512 + q * 128 + lane * 4); \
                _Pragma("unroll")                                              \
                for (int ks = 0; ks < 8; ks++) {                               \
                    const int q = ks >> 1; const int od = ks & 1;              \
                    mma_tf32(oacc[t], paf[ks],                                 \
                             od ? fv[q].z : fv[q].x,                           \
                             od ? fv[q].w : fv[q].y);                          \
                }                                                              \
            }                                                                  \
        }                                                                      \
        __syncthreads();                                                       \
    }

    TILE(0, 0);
#pragma unroll 1
    for (int jtm = 1; jtm < 16; jtm++) TILE(jtm, 1);
    TILE(16, 2);

    // ---- epilogue ----
    float inv0 = 1.0f / l0r, inv1 = 1.0f / l1r;
#pragma unroll
    for (int nt = 0; nt < 8; nt++) {
        int d = h * 64 + nt * 8 + l2;
        if (gi0 < NTOK)
            *(float2*)&out[((size_t)b * NTOK + gi0) * EMB + d] =
                make_float2(oacc[nt][0] * inv0, oacc[nt][1] * inv0);
        if (gi1 < NTOK)
            *(float2*)&out[((size_t)b * NTOK + gi1) * EMB + d] =
                make_float2(oacc[nt][2] * inv1, oacc[nt][3] * inv1);
    }
}

// ---------------------------------------------------------------------------
extern "C" void kernel_launch(void* const* d_in, const int* in_sizes, int n_in,
                              void* d_out, int out_size)
{
    const float* x      = (const float*)d_in[0];
    const float* qkv_w  = (const float*)d_in[1];  // [2304, 768]
    const float* qkv_b  = (const float*)d_in[2];  // [2304]
    const float* proj_w = (const float*)d_in[3];  // [768, 768]
    const float* proj_b = (const float*)d_in[4];  // [768]
    float* out = (float*)d_out;

    float *kvp = nullptr, *aop = nullptr, *btp = nullptr;
    unsigned *ktp = nullptr, *kfp = nullptr, *vfp = nullptr;
    cudaGetSymbolAddress((void**)&kvp, g_kv);
    cudaGetSymbolAddress((void**)&aop, g_ao);
    cudaGetSymbolAddress((void**)&btp, g_btab);
    cudaGetSymbolAddress((void**)&ktp, g_kt);
    cudaGetSymbolAddress((void**)&kfp, g_kf);
    cudaGetSymbolAddress((void**)&vfp, g_vf);

    const int attn_smem = (4 * FTBUF + 128 * STR) * 4;   // 100352 B

    static bool attr_set = false;
    if (!attr_set) {
        cudaFuncSetAttribute(attn_tf32, cudaFuncAttributeMaxDynamicSharedMemorySize,
                             attn_smem);
        attr_set = true;
    }

    init_btab<<<1, 256>>>(btp);

    // 1) kv = x @ qkv_w[768:2304].T + qkv_b[768:2304]   (q slice unused)
    gemm_tf32<<<dim3(1536 / 128, MTOT / 64), 256>>>(
        x, qkv_w + (size_t)768 * 768, qkv_b + 768, kvp, MTOT, 1536, 768);

    // 2) repack: plain Kt + q-major fragment Kf/Vf tiles
    repack_kv<<<dim3(NJT, HEADS, NB), 256>>>(kvp, ktp, kfp, vfp);

    // 3) flash attention (2 CTAs/SM target)
    attn_tf32<<<dim3(KPAD / 128, HEADS, NB), 256, attn_smem>>>(
        ktp, kfp, vfp, btp, aop);

    // 4) out = ao @ proj_w.T + proj_b
    gemm_tf32<<<dim3(768 / 128, MTOT / 64), 256>>>(
        aop, proj_w, proj_b, out, MTOT, 768, 768);
}